// round 1
// baseline (speedup 1.0000x reference)
#include <cuda_runtime.h>

#define PDIM 128
#define HEADS 4
#define EDIM 32
#define NSEG 32
#define CAP 512
#define NMAX 4096

// Scratch (allocation-free rule: device globals)
__device__ float g_Q[NMAX * PDIM];
__device__ float g_K[NMAX * PDIM];
__device__ float g_V[NMAX * PDIM];
__device__ int   g_rowlist[NMAX];
__device__ int   g_segstart[NSEG + 1];

#define GEMM_SMEM_FLOATS (128*132 + 128*128)
#define ATTN_SMEM_FLOATS (CAP*33 + CAP*32 + 8*CAP + 8*32)

// ---------------------------------------------------------------------------
// Kernel 1: fused QKV projection.  Out[n,128] = inp[n,128] @ W[128,128] + b
// grid = (ceil(n/128), 3), block = 256, 8x8 microtile per thread.
// ---------------------------------------------------------------------------
__global__ __launch_bounds__(256)
void qkv_gemm(const float* __restrict__ inp,
              const float* __restrict__ Wq, const float* __restrict__ bq,
              const float* __restrict__ Wk, const float* __restrict__ bk,
              const float* __restrict__ Wv, const float* __restrict__ bv,
              int n)
{
    extern __shared__ float sm[];
    float* As = sm;               // [128][132] (padded rows, float4-alignable)
    float* Bs = sm + 128 * 132;   // [128][128]

    const int which = blockIdx.y;
    const float* W    = (which == 0) ? Wq : (which == 1) ? Wk : Wv;
    const float* bias = (which == 0) ? bq : (which == 1) ? bk : bv;
    float* Out        = (which == 0) ? g_Q : (which == 1) ? g_K : g_V;

    const int base = blockIdx.x * 128;
    const int tid = threadIdx.x;

    // Load A tile (rows base..base+127, all 128 k) as float4, transposed-pad layout
    const float4* A4 = (const float4*)inp;
    for (int i = tid; i < 128 * 32; i += 256) {
        int row = i >> 5, k4 = i & 31;
        float4 v = make_float4(0.f, 0.f, 0.f, 0.f);
        if (base + row < n) v = A4[(size_t)(base + row) * 32 + k4];
        *(float4*)&As[row * 132 + k4 * 4] = v;
    }
    // Load W tile
    const float4* W4 = (const float4*)W;
    for (int i = tid; i < 128 * 32; i += 256) {
        int k = i >> 5, c4 = i & 31;
        *(float4*)&Bs[k * 128 + c4 * 4] = W4[k * 32 + c4];
    }
    __syncthreads();

    const int tx = tid & 15, ty = tid >> 4;   // 16x16 thread grid
    float acc[8][8];
#pragma unroll
    for (int i = 0; i < 8; i++)
#pragma unroll
        for (int j = 0; j < 8; j++) acc[i][j] = 0.f;

#pragma unroll 4
    for (int k = 0; k < 128; k++) {
        float a[8], b[8];
#pragma unroll
        for (int i = 0; i < 8; i++) a[i] = As[(ty * 8 + i) * 132 + k];
        float4 b0 = *(const float4*)&Bs[k * 128 + tx * 8];
        float4 b1 = *(const float4*)&Bs[k * 128 + tx * 8 + 4];
        b[0] = b0.x; b[1] = b0.y; b[2] = b0.z; b[3] = b0.w;
        b[4] = b1.x; b[5] = b1.y; b[6] = b1.z; b[7] = b1.w;
#pragma unroll
        for (int i = 0; i < 8; i++)
#pragma unroll
            for (int j = 0; j < 8; j++) acc[i][j] = fmaf(a[i], b[j], acc[i][j]);
    }

    // Epilogue: add bias, write
    float bi[8];
#pragma unroll
    for (int j = 0; j < 8; j++) bi[j] = bias[tx * 8 + j];
#pragma unroll
    for (int i = 0; i < 8; i++) {
        int row = base + ty * 8 + i;
        if (row < n) {
            float4 o0, o1;
            o0.x = acc[i][0] + bi[0]; o0.y = acc[i][1] + bi[1];
            o0.z = acc[i][2] + bi[2]; o0.w = acc[i][3] + bi[3];
            o1.x = acc[i][4] + bi[4]; o1.y = acc[i][5] + bi[5];
            o1.z = acc[i][6] + bi[6]; o1.w = acc[i][7] + bi[7];
            *(float4*)&Out[(size_t)row * 128 + tx * 8]     = o0;
            *(float4*)&Out[(size_t)row * 128 + tx * 8 + 4] = o1;
        }
    }
}

// ---------------------------------------------------------------------------
// Kernel 2: deterministic stable sort of row indices by segment.
// Single block, 256 threads. Per-thread histograms + block exclusive scan.
// rowlist sorted by (pos, original index) -> fully deterministic fp order.
// ---------------------------------------------------------------------------
__global__ __launch_bounds__(256)
void build_seg(const int* __restrict__ pos, int n)
{
    __shared__ int cnt[NSEG * 256];   // flattened (s * 256 + t), s-major
    __shared__ int tsum[256];

    const int t = threadIdx.x;
    const int chunk = (n + 255) / 256;
    const int lo = t * chunk;
    const int hi = min(n, lo + chunk);

#pragma unroll
    for (int s = 0; s < NSEG; s++) cnt[s * 256 + t] = 0;
    __syncthreads();

    for (int i = lo; i < hi; i++) cnt[pos[i] * 256 + t]++;
    __syncthreads();

    // Exclusive scan over the flattened 8192-element array.
    // Thread t serially scans its contiguous 32 slots.
    {
        int sum = 0;
#pragma unroll
        for (int j = 0; j < 32; j++) {
            int v = cnt[t * 32 + j];
            cnt[t * 32 + j] = sum;
            sum += v;
        }
        tsum[t] = sum;
    }
    __syncthreads();
    if (t == 0) {
        int a = 0;
        for (int i = 0; i < 256; i++) { int v = tsum[i]; tsum[i] = a; a += v; }
    }
    __syncthreads();
    {
        int b = tsum[t];
#pragma unroll
        for (int j = 0; j < 32; j++) cnt[t * 32 + j] += b;
    }
    __syncthreads();

    if (t < NSEG) g_segstart[t] = cnt[t * 256 + 0];
    if (t == 0) g_segstart[NSEG] = n;

    // Stable scatter: slot (s,t) is private to thread t.
    for (int i = lo; i < hi; i++) {
        int s = pos[i];
        int idx = cnt[s * 256 + t]++;
        g_rowlist[idx] = i;
    }
}

// ---------------------------------------------------------------------------
// Kernel 3: per-segment per-head attention. grid = (NSEG, HEADS), block = 256.
// Fast path (len <= CAP): K/V segment tiles in SMEM, warp-per-query.
// Slow path (len > CAP, statistically never): global two-pass.
// ---------------------------------------------------------------------------
__global__ __launch_bounds__(256)
void seg_attn(float* __restrict__ out)
{
    extern __shared__ float sm[];
    float* Ks = sm;                       // [CAP][33] padded -> conflict-free column reads
    float* Vs = Ks + CAP * 33;            // [CAP][32]
    float* wb = Vs + CAP * 32;            // [8][CAP] per-warp softmax weights
    float* qb = wb + 8 * CAP;             // [8][32]  per-warp query vector staging

    const int s = blockIdx.x, h = blockIdx.y;
    const int start = g_segstart[s];
    const int len = g_segstart[s + 1] - start;
    if (len == 0) return;

    const int tid = threadIdx.x, lane = tid & 31, warp = tid >> 5;
    const int hoff = h * EDIM;
    const float scale = 0.17677669529663687f;   // 1/sqrt(32)

    if (len <= CAP) {
        // Stage K,V segment tiles
        for (int i = tid; i < len * EDIM; i += 256) {
            int j = i >> 5, e = i & 31;
            int row = g_rowlist[start + j];
            Ks[j * 33 + e] = g_K[(size_t)row * PDIM + hoff + e];
            Vs[j * 32 + e] = g_V[(size_t)row * PDIM + hoff + e];
        }
        __syncthreads();

        const int nk = (len + 31) >> 5;
        for (int q = warp; q < len; q += 8) {
            const int row = g_rowlist[start + q];
            qb[warp * 32 + lane] = g_Q[(size_t)row * PDIM + hoff + lane];
            __syncwarp();
            float qv[32];
#pragma unroll
            for (int e = 0; e < 32; e++) qv[e] = qb[warp * 32 + e];

            // Scores: lane handles keys lane, lane+32, ...
            float sc[16];
            float m = -1e30f;
#pragma unroll
            for (int kk = 0; kk < 16; kk++) {
                if (kk < nk) {
                    int j = kk * 32 + lane;
                    float v = -1e30f;
                    if (j < len) {
                        const float* kp = &Ks[j * 33];
                        float s0 = 0.f, s1 = 0.f, s2 = 0.f, s3 = 0.f;
#pragma unroll
                        for (int e = 0; e < 32; e += 4) {
                            s0 = fmaf(qv[e],     kp[e],     s0);
                            s1 = fmaf(qv[e + 1], kp[e + 1], s1);
                            s2 = fmaf(qv[e + 2], kp[e + 2], s2);
                            s3 = fmaf(qv[e + 3], kp[e + 3], s3);
                        }
                        v = (s0 + s1 + s2 + s3) * scale;
                    }
                    sc[kk] = v;
                    m = fmaxf(m, v);
                }
            }
#pragma unroll
            for (int o = 16; o > 0; o >>= 1) m = fmaxf(m, __shfl_xor_sync(0xffffffffu, m, o));
            float l = 0.f;
#pragma unroll
            for (int kk = 0; kk < 16; kk++) {
                if (kk < nk) { float e = __expf(sc[kk] - m); sc[kk] = e; l += e; }
            }
#pragma unroll
            for (int o = 16; o > 0; o >>= 1) l += __shfl_xor_sync(0xffffffffu, l, o);
            const float inv = 1.f / l;
#pragma unroll
            for (int kk = 0; kk < 16; kk++) {
                if (kk < nk) {
                    int j = kk * 32 + lane;
                    if (j < len) wb[warp * CAP + j] = sc[kk] * inv;
                }
            }
            __syncwarp();

            // PV: lane computes output dim e = lane
            float a0 = 0.f, a1 = 0.f, a2 = 0.f, a3 = 0.f;
            int j = 0;
            for (; j + 4 <= len; j += 4) {
                a0 = fmaf(wb[warp * CAP + j],     Vs[(j)     * 32 + lane], a0);
                a1 = fmaf(wb[warp * CAP + j + 1], Vs[(j + 1) * 32 + lane], a1);
                a2 = fmaf(wb[warp * CAP + j + 2], Vs[(j + 2) * 32 + lane], a2);
                a3 = fmaf(wb[warp * CAP + j + 3], Vs[(j + 3) * 32 + lane], a3);
            }
            for (; j < len; j++) a0 = fmaf(wb[warp * CAP + j], Vs[j * 32 + lane], a0);
            out[(size_t)row * PDIM + hoff + lane] = (a0 + a1) + (a2 + a3);
        }
    } else {
        // Slow path: global-memory two-pass (never expected for this input,
        // kept for correctness robustness).
        for (int q = warp; q < len; q += 8) {
            const int row = g_rowlist[start + q];
            qb[warp * 32 + lane] = g_Q[(size_t)row * PDIM + hoff + lane];
            __syncwarp();
            float qv[32];
#pragma unroll
            for (int e = 0; e < 32; e++) qv[e] = qb[warp * 32 + e];

            float m = -1e30f;
            for (int j = lane; j < len; j += 32) {
                const float* kp = &g_K[(size_t)g_rowlist[start + j] * PDIM + hoff];
                float sdot = 0.f;
#pragma unroll
                for (int e = 0; e < 32; e++) sdot = fmaf(qv[e], kp[e], sdot);
                m = fmaxf(m, sdot * scale);
            }
#pragma unroll
            for (int o = 16; o > 0; o >>= 1) m = fmaxf(m, __shfl_xor_sync(0xffffffffu, m, o));

            float l = 0.f;
            float accv[32];
#pragma unroll
            for (int e = 0; e < 32; e++) accv[e] = 0.f;
            for (int j = lane; j < len; j += 32) {
                int r2 = g_rowlist[start + j];
                const float* kp = &g_K[(size_t)r2 * PDIM + hoff];
                float sdot = 0.f;
#pragma unroll
                for (int e = 0; e < 32; e++) sdot = fmaf(qv[e], kp[e], sdot);
                float w = __expf(sdot * scale - m);
                l += w;
                const float* vp = &g_V[(size_t)r2 * PDIM + hoff];
#pragma unroll
                for (int e = 0; e < 32; e++) accv[e] = fmaf(w, vp[e], accv[e]);
            }
#pragma unroll
            for (int o = 16; o > 0; o >>= 1) l += __shfl_xor_sync(0xffffffffu, l, o);
#pragma unroll
            for (int e = 0; e < 32; e++) {
                float r = accv[e];
#pragma unroll
                for (int o = 16; o > 0; o >>= 1) r += __shfl_xor_sync(0xffffffffu, r, o);
                if (lane == 0) qb[warp * 32 + e] = r;
            }
            __syncwarp();
            out[(size_t)row * PDIM + hoff + lane] = qb[warp * 32 + lane] / l;
            __syncwarp();
        }
    }
}

// ---------------------------------------------------------------------------
extern "C" void kernel_launch(void* const* d_in, const int* in_sizes, int n_in,
                              void* d_out, int out_size)
{
    const float* inp = (const float*)d_in[0];
    const int*   pos = (const int*)d_in[1];
    const float* Wq  = (const float*)d_in[2];
    const float* bq  = (const float*)d_in[3];
    const float* Wk  = (const float*)d_in[4];
    const float* bk  = (const float*)d_in[5];
    const float* Wv  = (const float*)d_in[6];
    const float* bv  = (const float*)d_in[7];
    float* out = (float*)d_out;
    const int n = in_sizes[1];

    const int gemm_smem = GEMM_SMEM_FLOATS * (int)sizeof(float);
    const int attn_smem = ATTN_SMEM_FLOATS * (int)sizeof(float);
    cudaFuncSetAttribute(qkv_gemm, cudaFuncAttributeMaxDynamicSharedMemorySize, gemm_smem);
    cudaFuncSetAttribute(seg_attn, cudaFuncAttributeMaxDynamicSharedMemorySize, attn_smem);

    const int row_blocks = (n + 127) / 128;
    qkv_gemm<<<dim3(row_blocks, 3), 256, gemm_smem>>>(inp, Wq, bq, Wk, bk, Wv, bv, n);
    build_seg<<<1, 256>>>(pos, n);
    seg_attn<<<dim3(NSEG, HEADS), 256, attn_smem>>>(out);
}

// round 2
// speedup vs baseline: 1.1449x; 1.1449x over previous
#include <cuda_runtime.h>

#define PDIM 128
#define HEADS 4
#define EDIM 32
#define NSEG 32
#define CAP 256
#define NMAX 4096

// Scratch (allocation-free rule: device globals)
__device__ float g_Q[NMAX * PDIM];
__device__ float g_K[NMAX * PDIM];
__device__ float g_V[NMAX * PDIM];
__device__ int   g_rowlist[NMAX];
__device__ int   g_segstart[NSEG + 1];

// qkv: As[32][129] + Bs[128][128]
#define GEMM_SMEM_FLOATS (32 * 129 + 128 * 128)
// attn: Ks[256][33] + Vs[256][32] + QsT[32][260] + wbT[8][256][4] + rows[256 ints]
#define ATTN_SMEM_FLOATS (CAP * 33 + CAP * 32 + 32 * 260 + 8 * CAP * 4 + CAP)
#define QST_PITCH 260

// ---------------------------------------------------------------------------
// Kernel 1: QKV projection. Out[32-row tile, 128] = inp @ W + b
// grid = (n/32, 3), block = 256 (16x16), thread tile 2 rows x 8 cols.
// smem 82KB -> 2 CTAs/SM; As pitch 129 -> conflict-free a-loads.
// ---------------------------------------------------------------------------
__global__ __launch_bounds__(256, 2)
void qkv_gemm(const float* __restrict__ inp,
              const float* __restrict__ Wq, const float* __restrict__ bq,
              const float* __restrict__ Wk, const float* __restrict__ bk,
              const float* __restrict__ Wv, const float* __restrict__ bv,
              int n)
{
    extern __shared__ float sm[];
    float* As = sm;              // [32][129]
    float* Bs = sm + 32 * 129;   // [128][128]

    const int which = blockIdx.y;
    const float* W    = (which == 0) ? Wq : (which == 1) ? Wk : Wv;
    const float* bias = (which == 0) ? bq : (which == 1) ? bk : bv;
    float* Out        = (which == 0) ? g_Q : (which == 1) ? g_K : g_V;

    const int base = blockIdx.x * 32;
    const int tid = threadIdx.x;

    // Stage A tile: 32 rows x 32 float4, coalesced reads, scalar writes (pitch 129)
    const float4* A4 = (const float4*)inp;
    for (int i = tid; i < 32 * 32; i += 256) {
        int row = i >> 5, k4 = i & 31;
        float4 v = make_float4(0.f, 0.f, 0.f, 0.f);
        if (base + row < n) v = A4[(size_t)(base + row) * 32 + k4];
        float* p = &As[row * 129 + k4 * 4];
        p[0] = v.x; p[1] = v.y; p[2] = v.z; p[3] = v.w;
    }
    // Stage W (full 128x128), float4
    const float4* W4 = (const float4*)W;
    for (int i = tid; i < 128 * 32; i += 256) {
        int k = i >> 5, c4 = i & 31;
        *(float4*)&Bs[k * 128 + c4 * 4] = W4[k * 32 + c4];
    }
    __syncthreads();

    const int tx = tid & 15, ty = tid >> 4;   // cols tx*8..+7, rows ty*2..+1
    float acc[2][8];
#pragma unroll
    for (int i = 0; i < 2; i++)
#pragma unroll
        for (int j = 0; j < 8; j++) acc[i][j] = 0.f;

#pragma unroll 8
    for (int k = 0; k < 128; k++) {
        float a0 = As[(ty * 2)     * 129 + k];
        float a1 = As[(ty * 2 + 1) * 129 + k];
        float4 b0 = *(const float4*)&Bs[k * 128 + tx * 8];
        float4 b1 = *(const float4*)&Bs[k * 128 + tx * 8 + 4];
        acc[0][0] = fmaf(a0, b0.x, acc[0][0]); acc[0][1] = fmaf(a0, b0.y, acc[0][1]);
        acc[0][2] = fmaf(a0, b0.z, acc[0][2]); acc[0][3] = fmaf(a0, b0.w, acc[0][3]);
        acc[0][4] = fmaf(a0, b1.x, acc[0][4]); acc[0][5] = fmaf(a0, b1.y, acc[0][5]);
        acc[0][6] = fmaf(a0, b1.z, acc[0][6]); acc[0][7] = fmaf(a0, b1.w, acc[0][7]);
        acc[1][0] = fmaf(a1, b0.x, acc[1][0]); acc[1][1] = fmaf(a1, b0.y, acc[1][1]);
        acc[1][2] = fmaf(a1, b0.z, acc[1][2]); acc[1][3] = fmaf(a1, b0.w, acc[1][3]);
        acc[1][4] = fmaf(a1, b1.x, acc[1][4]); acc[1][5] = fmaf(a1, b1.y, acc[1][5]);
        acc[1][6] = fmaf(a1, b1.z, acc[1][6]); acc[1][7] = fmaf(a1, b1.w, acc[1][7]);
    }

    float bi[8];
#pragma unroll
    for (int j = 0; j < 8; j++) bi[j] = bias[tx * 8 + j];
#pragma unroll
    for (int i = 0; i < 2; i++) {
        int row = base + ty * 2 + i;
        if (row < n) {
            float4 o0, o1;
            o0.x = acc[i][0] + bi[0]; o0.y = acc[i][1] + bi[1];
            o0.z = acc[i][2] + bi[2]; o0.w = acc[i][3] + bi[3];
            o1.x = acc[i][4] + bi[4]; o1.y = acc[i][5] + bi[5];
            o1.z = acc[i][6] + bi[6]; o1.w = acc[i][7] + bi[7];
            *(float4*)&Out[(size_t)row * 128 + tx * 8]     = o0;
            *(float4*)&Out[(size_t)row * 128 + tx * 8 + 4] = o1;
        }
    }
}

// ---------------------------------------------------------------------------
// Kernel 2: deterministic stable counting sort of rows by segment.
// ---------------------------------------------------------------------------
__global__ __launch_bounds__(256)
void build_seg(const int* __restrict__ pos, int n)
{
    __shared__ int cnt[NSEG * 256];
    __shared__ int tsum[256];

    const int t = threadIdx.x;
    const int chunk = (n + 255) / 256;
    const int lo = t * chunk;
    const int hi = min(n, lo + chunk);

#pragma unroll
    for (int s = 0; s < NSEG; s++) cnt[s * 256 + t] = 0;
    __syncthreads();

    for (int i = lo; i < hi; i++) cnt[pos[i] * 256 + t]++;
    __syncthreads();

    {
        int sum = 0;
#pragma unroll
        for (int j = 0; j < 32; j++) {
            int v = cnt[t * 32 + j];
            cnt[t * 32 + j] = sum;
            sum += v;
        }
        tsum[t] = sum;
    }
    __syncthreads();
    if (t == 0) {
        int a = 0;
        for (int i = 0; i < 256; i++) { int v = tsum[i]; tsum[i] = a; a += v; }
    }
    __syncthreads();
    {
        int b = tsum[t];
#pragma unroll
        for (int j = 0; j < 32; j++) cnt[t * 32 + j] += b;
    }
    __syncthreads();

    if (t < NSEG) g_segstart[t] = cnt[t * 256 + 0];
    if (t == 0) g_segstart[NSEG] = n;

    for (int i = lo; i < hi; i++) {
        int s = pos[i];
        int idx = cnt[s * 256 + t]++;
        g_rowlist[idx] = i;
    }
}

// ---------------------------------------------------------------------------
// Kernel 3: per-segment per-head attention, 4-query-per-warp batching.
// grid = (NSEG, HEADS), block = 256 (8 warps).
// ---------------------------------------------------------------------------
__global__ __launch_bounds__(256)
void seg_attn(float* __restrict__ out)
{
    extern __shared__ float sm[];
    float* Ks  = sm;                          // [CAP][33]
    float* Vs  = Ks + CAP * 33;               // [CAP][32]
    float* QsT = Vs + CAP * 32;               // [32][QST_PITCH] transposed queries
    float* wbT = QsT + 32 * QST_PITCH;        // [8 warps][CAP][4] per-key float4 weights
    int*  rows = (int*)(wbT + 8 * CAP * 4);   // [CAP]

    const int s = blockIdx.x, h = blockIdx.y;
    const int start = g_segstart[s];
    const int len = g_segstart[s + 1] - start;
    if (len == 0) return;

    const int tid = threadIdx.x, lane = tid & 31, warp = tid >> 5;
    const int hoff = h * EDIM;
    const float scale = 0.17677669529663687f;   // 1/sqrt(32)

    if (len <= CAP) {
        if (tid < len) rows[tid] = g_rowlist[start + tid];
        // Stage K, V, Q (Q transposed)
        for (int i = tid; i < len * EDIM; i += 256) {
            int j = i >> 5, e = i & 31;
            int row = g_rowlist[start + j];
            float kv = g_K[(size_t)row * PDIM + hoff + e];
            Ks[j * 33 + e] = kv;
            Vs[j * 32 + e] = g_V[(size_t)row * PDIM + hoff + e];
            QsT[e * QST_PITCH + j] = g_Q[(size_t)row * PDIM + hoff + e];
        }
        __syncthreads();

        const int nk = (len + 31) >> 5;
        float* wbW = wbT + warp * (CAP * 4);

        for (int qb = warp * 4; qb < len; qb += 32) {
            // ---- scores: lane = key j within chunk, 4 queries at once ----
            float sc[4][8];
#pragma unroll
            for (int kk = 0; kk < 8; kk++) {
                if (kk < nk) {
                    int j = kk * 32 + lane;
                    float a0 = 0.f, a1 = 0.f, a2 = 0.f, a3 = 0.f;
                    const float* kp = &Ks[j * 33];
#pragma unroll
                    for (int e = 0; e < 32; e++) {
                        float ke = kp[e];
                        float4 q4 = *(const float4*)&QsT[e * QST_PITCH + qb];
                        a0 = fmaf(ke, q4.x, a0);
                        a1 = fmaf(ke, q4.y, a1);
                        a2 = fmaf(ke, q4.z, a2);
                        a3 = fmaf(ke, q4.w, a3);
                    }
                    bool valid = (j < len);
                    sc[0][kk] = valid ? a0 * scale : -1e30f;
                    sc[1][kk] = valid ? a1 * scale : -1e30f;
                    sc[2][kk] = valid ? a2 * scale : -1e30f;
                    sc[3][kk] = valid ? a3 * scale : -1e30f;
                }
            }
            // ---- softmax per query ----
            float inv[4];
#pragma unroll
            for (int qi = 0; qi < 4; qi++) {
                float m = -1e30f;
#pragma unroll
                for (int kk = 0; kk < 8; kk++)
                    if (kk < nk) m = fmaxf(m, sc[qi][kk]);
#pragma unroll
                for (int o = 16; o > 0; o >>= 1)
                    m = fmaxf(m, __shfl_xor_sync(0xffffffffu, m, o));
                float l = 0.f;
#pragma unroll
                for (int kk = 0; kk < 8; kk++) {
                    if (kk < nk) {
                        float e = __expf(sc[qi][kk] - m);
                        sc[qi][kk] = e;
                        l += e;
                    }
                }
#pragma unroll
                for (int o = 16; o > 0; o >>= 1)
                    l += __shfl_xor_sync(0xffffffffu, l, o);
                inv[qi] = 1.f / l;
            }
            // ---- store weights as float4 per key ----
#pragma unroll
            for (int kk = 0; kk < 8; kk++) {
                if (kk < nk) {
                    int j = kk * 32 + lane;
                    float4 w;
                    w.x = sc[0][kk] * inv[0];
                    w.y = sc[1][kk] * inv[1];
                    w.z = sc[2][kk] * inv[2];
                    w.w = sc[3][kk] * inv[3];
                    *(float4*)&wbW[j * 4] = w;
                }
            }
            __syncwarp();

            // ---- PV: lane = embed dim e, 4 queries at once ----
            float a0 = 0.f, a1 = 0.f, a2 = 0.f, a3 = 0.f;
            int j = 0;
            for (; j + 2 <= len; j += 2) {
                float v0 = Vs[j * 32 + lane];
                float4 w0 = *(const float4*)&wbW[j * 4];
                float v1 = Vs[(j + 1) * 32 + lane];
                float4 w1 = *(const float4*)&wbW[(j + 1) * 4];
                a0 = fmaf(w0.x, v0, a0); a1 = fmaf(w0.y, v0, a1);
                a2 = fmaf(w0.z, v0, a2); a3 = fmaf(w0.w, v0, a3);
                a0 = fmaf(w1.x, v1, a0); a1 = fmaf(w1.y, v1, a1);
                a2 = fmaf(w1.z, v1, a2); a3 = fmaf(w1.w, v1, a3);
            }
            for (; j < len; j++) {
                float v0 = Vs[j * 32 + lane];
                float4 w0 = *(const float4*)&wbW[j * 4];
                a0 = fmaf(w0.x, v0, a0); a1 = fmaf(w0.y, v0, a1);
                a2 = fmaf(w0.z, v0, a2); a3 = fmaf(w0.w, v0, a3);
            }

            // ---- write 4 query outputs ----
            if (qb + 0 < len) out[(size_t)rows[qb + 0] * PDIM + hoff + lane] = a0;
            if (qb + 1 < len) out[(size_t)rows[qb + 1] * PDIM + hoff + lane] = a1;
            if (qb + 2 < len) out[(size_t)rows[qb + 2] * PDIM + hoff + lane] = a2;
            if (qb + 3 < len) out[(size_t)rows[qb + 3] * PDIM + hoff + lane] = a3;
            __syncwarp();
        }
    } else {
        // Slow path (len > CAP, statistically never): global two-pass.
        float* qb = QsT;   // reuse smem: [8][32]
        for (int q = warp; q < len; q += 8) {
            const int row = g_rowlist[start + q];
            qb[warp * 32 + lane] = g_Q[(size_t)row * PDIM + hoff + lane];
            __syncwarp();
            float qv[32];
#pragma unroll
            for (int e = 0; e < 32; e++) qv[e] = qb[warp * 32 + e];

            float m = -1e30f;
            for (int j = lane; j < len; j += 32) {
                const float* kp = &g_K[(size_t)g_rowlist[start + j] * PDIM + hoff];
                float sdot = 0.f;
#pragma unroll
                for (int e = 0; e < 32; e++) sdot = fmaf(qv[e], kp[e], sdot);
                m = fmaxf(m, sdot * scale);
            }
#pragma unroll
            for (int o = 16; o > 0; o >>= 1) m = fmaxf(m, __shfl_xor_sync(0xffffffffu, m, o));

            float l = 0.f;
            float accv[32];
#pragma unroll
            for (int e = 0; e < 32; e++) accv[e] = 0.f;
            for (int j = lane; j < len; j += 32) {
                int r2 = g_rowlist[start + j];
                const float* kp = &g_K[(size_t)r2 * PDIM + hoff];
                float sdot = 0.f;
#pragma unroll
                for (int e = 0; e < 32; e++) sdot = fmaf(qv[e], kp[e], sdot);
                float w = __expf(sdot * scale - m);
                l += w;
                const float* vp = &g_V[(size_t)r2 * PDIM + hoff];
#pragma unroll
                for (int e = 0; e < 32; e++) accv[e] = fmaf(w, vp[e], accv[e]);
            }
#pragma unroll
            for (int o = 16; o > 0; o >>= 1) l += __shfl_xor_sync(0xffffffffu, l, o);
#pragma unroll
            for (int e = 0; e < 32; e++) {
                float r = accv[e];
#pragma unroll
                for (int o = 16; o > 0; o >>= 1) r += __shfl_xor_sync(0xffffffffu, r, o);
                if (lane == 0) qb[warp * 32 + e] = r;
            }
            __syncwarp();
            out[(size_t)row * PDIM + hoff + lane] = qb[warp * 32 + lane] / l;
            __syncwarp();
        }
    }
}

// ---------------------------------------------------------------------------
extern "C" void kernel_launch(void* const* d_in, const int* in_sizes, int n_in,
                              void* d_out, int out_size)
{
    const float* inp = (const float*)d_in[0];
    const int*   pos = (const int*)d_in[1];
    const float* Wq  = (const float*)d_in[2];
    const float* bq  = (const float*)d_in[3];
    const float* Wk  = (const float*)d_in[4];
    const float* bk  = (const float*)d_in[5];
    const float* Wv  = (const float*)d_in[6];
    const float* bv  = (const float*)d_in[7];
    float* out = (float*)d_out;
    const int n = in_sizes[1];

    const int gemm_smem = GEMM_SMEM_FLOATS * (int)sizeof(float);
    const int attn_smem = ATTN_SMEM_FLOATS * (int)sizeof(float) + CAP * (int)sizeof(int);
    cudaFuncSetAttribute(qkv_gemm, cudaFuncAttributeMaxDynamicSharedMemorySize, gemm_smem);
    cudaFuncSetAttribute(seg_attn, cudaFuncAttributeMaxDynamicSharedMemorySize, attn_smem);

    const int row_blocks = (n + 31) / 32;
    qkv_gemm<<<dim3(row_blocks, 3), 256, gemm_smem>>>(inp, Wq, bq, Wk, bk, Wv, bv, n);
    build_seg<<<1, 256>>>(pos, n);
    seg_attn<<<dim3(NSEG, HEADS), 256, attn_smem>>>(out);
}

// round 3
// speedup vs baseline: 1.3694x; 1.1961x over previous
#include <cuda_runtime.h>

#define PDIM 128
#define HEADS 4
#define EDIM 32
#define NSEG 32
#define CAP 256
#define NMAX 4096
#define QST_PITCH 260
#define ATTN_THREADS 512
#define ATTN_WARPS 16

// Scratch (allocation-free rule: device globals)
__device__ float g_Q[NMAX * PDIM];
__device__ float g_K[NMAX * PDIM];
__device__ float g_V[NMAX * PDIM];
__device__ int   g_rowlist[NMAX];
__device__ int   g_segstart[NSEG + 1];

// qkv: W tile only
#define GEMM_SMEM_BYTES (128 * 128 * 4)
// attn: Ks[CAP][33] + Vs[CAP][32] + QsT[32][260] + wbT[16][CAP][4] + rows[CAP]
#define ATTN_SMEM_BYTES ((CAP*33 + CAP*32 + 32*QST_PITCH + ATTN_WARPS*CAP*4) * 4 + CAP * 4)

// ---------------------------------------------------------------------------
// Kernel 1: QKV projection. grid (n/32, 3), block 256.
// W in smem (64KB -> 3 CTAs/SM). A streamed from global into regs
// (all lanes of a warp share the same 4 rows -> broadcast sectors).
// Thread tile 4 rows x 4 cols -> 1 LDS.128 per 16 FMA (1 B/FMA smem traffic).
// ---------------------------------------------------------------------------
__global__ __launch_bounds__(256, 3)
void qkv_gemm(const float* __restrict__ inp,
              const float* __restrict__ Wq, const float* __restrict__ bq,
              const float* __restrict__ Wk, const float* __restrict__ bk,
              const float* __restrict__ Wv, const float* __restrict__ bv,
              int n)
{
    extern __shared__ float sm[];
    float4* Bs4 = (float4*)sm;            // [128][32] float4  (row k, 32 col-groups)

    const int which = blockIdx.y;
    const float* W    = (which == 0) ? Wq : (which == 1) ? Wk : Wv;
    const float* bias = (which == 0) ? bq : (which == 1) ? bk : bv;
    float* Out        = (which == 0) ? g_Q : (which == 1) ? g_K : g_V;

    const int base = blockIdx.x * 32;
    const int tid  = threadIdx.x;

    // Stage W (128x128) as float4, coalesced
    const float4* W4 = (const float4*)W;
    for (int i = tid; i < 128 * 32; i += 256) Bs4[i] = W4[i];
    __syncthreads();

    const int tx = tid & 31;          // col group: cols tx*4..+3
    const int ty = tid >> 5;          // row group: rows base+ty*4..+3 (== warp id)
    const int r0 = base + ty * 4;

    const float4* A4 = (const float4*)inp;
    float4 acc[4];
#pragma unroll
    for (int i = 0; i < 4; i++) acc[i] = make_float4(0.f, 0.f, 0.f, 0.f);

    // row clamp (n may not be multiple of 32; clamp loads, guard stores)
    int r[4];
#pragma unroll
    for (int i = 0; i < 4; i++) r[i] = min(r0 + i, n - 1);

#pragma unroll 4
    for (int kc = 0; kc < 32; kc++) {          // k in chunks of 4
        float4 a[4];
#pragma unroll
        for (int i = 0; i < 4; i++) a[i] = A4[(size_t)r[i] * 32 + kc];
#pragma unroll
        for (int kk = 0; kk < 4; kk++) {
            float4 b = Bs4[(kc * 4 + kk) * 32 + tx];
            float a0 = ((const float*)&a[0])[kk];
            float a1 = ((const float*)&a[1])[kk];
            float a2 = ((const float*)&a[2])[kk];
            float a3 = ((const float*)&a[3])[kk];
            acc[0].x = fmaf(a0, b.x, acc[0].x); acc[0].y = fmaf(a0, b.y, acc[0].y);
            acc[0].z = fmaf(a0, b.z, acc[0].z); acc[0].w = fmaf(a0, b.w, acc[0].w);
            acc[1].x = fmaf(a1, b.x, acc[1].x); acc[1].y = fmaf(a1, b.y, acc[1].y);
            acc[1].z = fmaf(a1, b.z, acc[1].z); acc[1].w = fmaf(a1, b.w, acc[1].w);
            acc[2].x = fmaf(a2, b.x, acc[2].x); acc[2].y = fmaf(a2, b.y, acc[2].y);
            acc[2].z = fmaf(a2, b.z, acc[2].z); acc[2].w = fmaf(a2, b.w, acc[2].w);
            acc[3].x = fmaf(a3, b.x, acc[3].x); acc[3].y = fmaf(a3, b.y, acc[3].y);
            acc[3].z = fmaf(a3, b.z, acc[3].z); acc[3].w = fmaf(a3, b.w, acc[3].w);
        }
    }

    float4 bi = ((const float4*)bias)[tx];
#pragma unroll
    for (int i = 0; i < 4; i++) {
        int row = r0 + i;
        if (row < n) {
            float4 o;
            o.x = acc[i].x + bi.x; o.y = acc[i].y + bi.y;
            o.z = acc[i].z + bi.z; o.w = acc[i].w + bi.w;
            ((float4*)Out)[(size_t)row * 32 + tx] = o;
        }
    }
}

// ---------------------------------------------------------------------------
// Kernel 2: deterministic stable counting sort of rows by segment.
// ---------------------------------------------------------------------------
__global__ __launch_bounds__(256)
void build_seg(const int* __restrict__ pos, int n)
{
    __shared__ int cnt[NSEG * 256];
    __shared__ int tsum[256];

    const int t = threadIdx.x;
    const int chunk = (n + 255) / 256;
    const int lo = t * chunk;
    const int hi = min(n, lo + chunk);

#pragma unroll
    for (int s = 0; s < NSEG; s++) cnt[s * 256 + t] = 0;
    __syncthreads();

    for (int i = lo; i < hi; i++) cnt[pos[i] * 256 + t]++;
    __syncthreads();

    {
        int sum = 0;
#pragma unroll
        for (int j = 0; j < 32; j++) {
            int v = cnt[t * 32 + j];
            cnt[t * 32 + j] = sum;
            sum += v;
        }
        tsum[t] = sum;
    }
    __syncthreads();
    if (t == 0) {
        int a = 0;
        for (int i = 0; i < 256; i++) { int v = tsum[i]; tsum[i] = a; a += v; }
    }
    __syncthreads();
    {
        int b = tsum[t];
#pragma unroll
        for (int j = 0; j < 32; j++) cnt[t * 32 + j] += b;
    }
    __syncthreads();

    if (t < NSEG) g_segstart[t] = cnt[t * 256 + 0];
    if (t == 0) g_segstart[NSEG] = n;

    for (int i = lo; i < hi; i++) {
        int s = pos[i];
        int idx = cnt[s * 256 + t]++;
        g_rowlist[idx] = i;
    }
}

// ---------------------------------------------------------------------------
// Kernel 3: per-segment per-head attention.
// grid (NSEG, HEADS), block 512 (16 warps), 4 queries per warp.
// ---------------------------------------------------------------------------
__global__ __launch_bounds__(ATTN_THREADS)
void seg_attn(float* __restrict__ out)
{
    extern __shared__ float sm[];
    float* Ks  = sm;                          // [CAP][33]
    float* Vs  = Ks + CAP * 33;               // [CAP][32]
    float* QsT = Vs + CAP * 32;               // [32][QST_PITCH]
    float* wbT = QsT + 32 * QST_PITCH;        // [16 warps][CAP][4]
    int*  rows = (int*)(wbT + ATTN_WARPS * CAP * 4);   // [CAP]

    const int s = blockIdx.x, h = blockIdx.y;
    const int start = g_segstart[s];
    const int len = g_segstart[s + 1] - start;
    if (len == 0) return;

    const int tid = threadIdx.x, lane = tid & 31, warp = tid >> 5;
    const int hoff = h * EDIM;
    const float scale = 0.17677669529663687f;   // 1/sqrt(32)

    if (len <= CAP) {
        if (tid < len) rows[tid] = g_rowlist[start + tid];
        for (int i = tid; i < len * EDIM; i += ATTN_THREADS) {
            int j = i >> 5, e = i & 31;
            int row = g_rowlist[start + j];
            Ks[j * 33 + e] = g_K[(size_t)row * PDIM + hoff + e];
            Vs[j * 32 + e] = g_V[(size_t)row * PDIM + hoff + e];
            QsT[e * QST_PITCH + j] = g_Q[(size_t)row * PDIM + hoff + e];
        }
        __syncthreads();

        const int nk = (len + 31) >> 5;
        float* wbW = wbT + warp * (CAP * 4);

        for (int qb = warp * 4; qb < len; qb += ATTN_WARPS * 4) {
            // ---- scores: lane = key within chunk, 4 queries at once ----
            float sc[4][8];
#pragma unroll
            for (int kk = 0; kk < 8; kk++) {
                if (kk < nk) {
                    int j = kk * 32 + lane;
                    float a0 = 0.f, a1 = 0.f, a2 = 0.f, a3 = 0.f;
                    const float* kp = &Ks[j * 33];
#pragma unroll
                    for (int e = 0; e < 32; e++) {
                        float ke = kp[e];
                        float4 q4 = *(const float4*)&QsT[e * QST_PITCH + qb];
                        a0 = fmaf(ke, q4.x, a0);
                        a1 = fmaf(ke, q4.y, a1);
                        a2 = fmaf(ke, q4.z, a2);
                        a3 = fmaf(ke, q4.w, a3);
                    }
                    bool valid = (j < len);
                    sc[0][kk] = valid ? a0 * scale : -1e30f;
                    sc[1][kk] = valid ? a1 * scale : -1e30f;
                    sc[2][kk] = valid ? a2 * scale : -1e30f;
                    sc[3][kk] = valid ? a3 * scale : -1e30f;
                }
            }
            // ---- softmax per query ----
            float inv[4];
#pragma unroll
            for (int qi = 0; qi < 4; qi++) {
                float m = -1e30f;
#pragma unroll
                for (int kk = 0; kk < 8; kk++)
                    if (kk < nk) m = fmaxf(m, sc[qi][kk]);
#pragma unroll
                for (int o = 16; o > 0; o >>= 1)
                    m = fmaxf(m, __shfl_xor_sync(0xffffffffu, m, o));
                float l = 0.f;
#pragma unroll
                for (int kk = 0; kk < 8; kk++) {
                    if (kk < nk) {
                        float e = __expf(sc[qi][kk] - m);
                        sc[qi][kk] = e;
                        l += e;
                    }
                }
#pragma unroll
                for (int o = 16; o > 0; o >>= 1)
                    l += __shfl_xor_sync(0xffffffffu, l, o);
                inv[qi] = 1.f / l;
            }
            // ---- store weights as float4 per key ----
#pragma unroll
            for (int kk = 0; kk < 8; kk++) {
                if (kk < nk) {
                    int j = kk * 32 + lane;
                    float4 w;
                    w.x = sc[0][kk] * inv[0];
                    w.y = sc[1][kk] * inv[1];
                    w.z = sc[2][kk] * inv[2];
                    w.w = sc[3][kk] * inv[3];
                    *(float4*)&wbW[j * 4] = w;
                }
            }
            __syncwarp();

            // ---- PV: lane = embed dim, 4 queries at once ----
            float a0 = 0.f, a1 = 0.f, a2 = 0.f, a3 = 0.f;
            int j = 0;
            for (; j + 2 <= len; j += 2) {
                float v0 = Vs[j * 32 + lane];
                float4 w0 = *(const float4*)&wbW[j * 4];
                float v1 = Vs[(j + 1) * 32 + lane];
                float4 w1 = *(const float4*)&wbW[(j + 1) * 4];
                a0 = fmaf(w0.x, v0, a0); a1 = fmaf(w0.y, v0, a1);
                a2 = fmaf(w0.z, v0, a2); a3 = fmaf(w0.w, v0, a3);
                a0 = fmaf(w1.x, v1, a0); a1 = fmaf(w1.y, v1, a1);
                a2 = fmaf(w1.z, v1, a2); a3 = fmaf(w1.w, v1, a3);
            }
            for (; j < len; j++) {
                float v0 = Vs[j * 32 + lane];
                float4 w0 = *(const float4*)&wbW[j * 4];
                a0 = fmaf(w0.x, v0, a0); a1 = fmaf(w0.y, v0, a1);
                a2 = fmaf(w0.z, v0, a2); a3 = fmaf(w0.w, v0, a3);
            }

            if (qb + 0 < len) out[(size_t)rows[qb + 0] * PDIM + hoff + lane] = a0;
            if (qb + 1 < len) out[(size_t)rows[qb + 1] * PDIM + hoff + lane] = a1;
            if (qb + 2 < len) out[(size_t)rows[qb + 2] * PDIM + hoff + lane] = a2;
            if (qb + 3 < len) out[(size_t)rows[qb + 3] * PDIM + hoff + lane] = a3;
            __syncwarp();
        }
    } else {
        // Slow path (len > CAP, statistically never): global two-pass.
        float* qb = QsT;   // reuse smem: [ATTN_WARPS][32]
        for (int q = warp; q < len; q += ATTN_WARPS) {
            const int row = g_rowlist[start + q];
            qb[warp * 32 + lane] = g_Q[(size_t)row * PDIM + hoff + lane];
            __syncwarp();
            float qv[32];
#pragma unroll
            for (int e = 0; e < 32; e++) qv[e] = qb[warp * 32 + e];

            float m = -1e30f;
            for (int j = lane; j < len; j += 32) {
                const float* kp = &g_K[(size_t)g_rowlist[start + j] * PDIM + hoff];
                float sdot = 0.f;
#pragma unroll
                for (int e = 0; e < 32; e++) sdot = fmaf(qv[e], kp[e], sdot);
                m = fmaxf(m, sdot * scale);
            }
#pragma unroll
            for (int o = 16; o > 0; o >>= 1) m = fmaxf(m, __shfl_xor_sync(0xffffffffu, m, o));

            float l = 0.f;
            float accv[32];
#pragma unroll
            for (int e = 0; e < 32; e++) accv[e] = 0.f;
            for (int j = lane; j < len; j += 32) {
                int r2 = g_rowlist[start + j];
                const float* kp = &g_K[(size_t)r2 * PDIM + hoff];
                float sdot = 0.f;
#pragma unroll
                for (int e = 0; e < 32; e++) sdot = fmaf(qv[e], kp[e], sdot);
                float w = __expf(sdot * scale - m);
                l += w;
                const float* vp = &g_V[(size_t)r2 * PDIM + hoff];
#pragma unroll
                for (int e = 0; e < 32; e++) accv[e] = fmaf(w, vp[e], accv[e]);
            }
#pragma unroll
            for (int o = 16; o > 0; o >>= 1) l += __shfl_xor_sync(0xffffffffu, l, o);
#pragma unroll
            for (int e = 0; e < 32; e++) {
                float r = accv[e];
#pragma unroll
                for (int o = 16; o > 0; o >>= 1) r += __shfl_xor_sync(0xffffffffu, r, o);
                if (lane == 0) qb[warp * 32 + e] = r;
            }
            __syncwarp();
            out[(size_t)row * PDIM + hoff + lane] = qb[warp * 32 + lane] / l;
            __syncwarp();
        }
    }
}

// ---------------------------------------------------------------------------
extern "C" void kernel_launch(void* const* d_in, const int* in_sizes, int n_in,
                              void* d_out, int out_size)
{
    const float* inp = (const float*)d_in[0];
    const int*   pos = (const int*)d_in[1];
    const float* Wq  = (const float*)d_in[2];
    const float* bq  = (const float*)d_in[3];
    const float* Wk  = (const float*)d_in[4];
    const float* bk  = (const float*)d_in[5];
    const float* Wv  = (const float*)d_in[6];
    const float* bv  = (const float*)d_in[7];
    float* out = (float*)d_out;
    const int n = in_sizes[1];

    cudaFuncSetAttribute(qkv_gemm, cudaFuncAttributeMaxDynamicSharedMemorySize, GEMM_SMEM_BYTES);
    cudaFuncSetAttribute(seg_attn, cudaFuncAttributeMaxDynamicSharedMemorySize, ATTN_SMEM_BYTES);

    const int row_blocks = (n + 31) / 32;
    qkv_gemm<<<dim3(row_blocks, 3), 256, GEMM_SMEM_BYTES>>>(inp, Wq, bq, Wk, bk, Wv, bv, n);
    build_seg<<<1, 256>>>(pos, n);
    seg_attn<<<dim3(NSEG, HEADS), ATTN_THREADS, ATTN_SMEM_BYTES>>>(out);
}

// round 4
// speedup vs baseline: 1.6739x; 1.2223x over previous
#include <cuda_runtime.h>

#define PDIM 128
#define HEADS 4
#define EDIM 32
#define NSEG 32
#define CAP 256
#define NMAX 4096
#define QST_PITCH 260
#define NK_MAX (CAP / 32)

// Scratch (allocation-free rule: device globals)
__device__ float g_Q[NMAX * PDIM];
__device__ float g_K[NMAX * PDIM];
__device__ float g_V[NMAX * PDIM];
__device__ int   g_rowlist[NMAX];
__device__ int   g_segstart[NSEG + 1];

// fused qkv+build: max(W half-tile 32KB, build scratch 34KB)
#define QKV_SMEM_BYTES (NSEG * 256 * 4 + 256 * 4 + 256)
// attn: Ks[256][33] + Vs[256][32] + QsT[32][260] + wb[32][32][4] + rows[256]
#define ATTN_SMEM_BYTES ((CAP*33 + CAP*32 + 32*QST_PITCH + 32*32*4) * 4 + CAP * 4)

// ---------------------------------------------------------------------------
// Kernel 1 (fused): QKV projection + segment build.
// grid (n/32, 7), block 256.
//  y in [0,6): which = y>>1, col-half = y&1. Tile = 32 rows x 64 cols.
//  W half-tile (32KB) in smem -> 5 CTAs/SM. A rows broadcast-loaded from global.
//  y == 6, x == 0: deterministic stable counting sort of rows by segment
//  (independent of the GEMM work; runs concurrently).
// ---------------------------------------------------------------------------
__global__ __launch_bounds__(256, 5)
void qkv_build(const float* __restrict__ inp,
               const float* __restrict__ Wq, const float* __restrict__ bq,
               const float* __restrict__ Wk, const float* __restrict__ bk,
               const float* __restrict__ Wv, const float* __restrict__ bv,
               const int* __restrict__ pos, int n)
{
    extern __shared__ float sm[];
    const int y = blockIdx.y;
    const int tid = threadIdx.x;

    if (y == 6) {
        // ---------------- build_seg path ----------------
        if (blockIdx.x != 0) return;
        int* cnt  = (int*)sm;            // [NSEG*256]
        int* tsum = cnt + NSEG * 256;    // [256]

        const int t = tid;
        const int chunk = (n + 255) / 256;
        const int lo = t * chunk;
        const int hi = min(n, lo + chunk);

#pragma unroll
        for (int s = 0; s < NSEG; s++) cnt[s * 256 + t] = 0;
        __syncthreads();
        for (int i = lo; i < hi; i++) cnt[pos[i] * 256 + t]++;
        __syncthreads();
        {
            int sum = 0;
#pragma unroll
            for (int j = 0; j < 32; j++) {
                int v = cnt[t * 32 + j];
                cnt[t * 32 + j] = sum;
                sum += v;
            }
            tsum[t] = sum;
        }
        __syncthreads();
        if (t == 0) {
            int a = 0;
            for (int i = 0; i < 256; i++) { int v = tsum[i]; tsum[i] = a; a += v; }
        }
        __syncthreads();
        {
            int b = tsum[t];
#pragma unroll
            for (int j = 0; j < 32; j++) cnt[t * 32 + j] += b;
        }
        __syncthreads();
        if (t < NSEG) g_segstart[t] = cnt[t * 256 + 0];
        if (t == 0) g_segstart[NSEG] = n;
        for (int i = lo; i < hi; i++) {
            int s = pos[i];
            int idx = cnt[s * 256 + t]++;
            g_rowlist[idx] = i;
        }
        return;
    }

    // ---------------- GEMM path ----------------
    const int which = y >> 1;
    const int colh  = y & 1;
    const float* W    = (which == 0) ? Wq : (which == 1) ? Wk : Wv;
    const float* bias = (which == 0) ? bq : (which == 1) ? bk : bv;
    float* Out        = (which == 0) ? g_Q : (which == 1) ? g_K : g_V;

    float4* Bs4 = (float4*)sm;           // [128][16] float4 (64 cols)

    // Stage W half: rows 0..127, cols colh*64..+63
    const float4* W4 = (const float4*)W;
    for (int i = tid; i < 128 * 16; i += 256) {
        int k = i >> 4, c = i & 15;
        Bs4[i] = W4[k * 32 + colh * 16 + c];
    }
    __syncthreads();

    const int base = blockIdx.x * 32;
    const int tx = tid & 15;             // col4 group within the 64-col half
    const int ty = tid >> 4;             // row pair
    const int r0 = base + ty * 2;

    const float4* A4 = (const float4*)inp;
    int ra = min(r0,     n - 1);
    int rb = min(r0 + 1, n - 1);

    float4 acc0 = make_float4(0.f, 0.f, 0.f, 0.f);
    float4 acc1 = make_float4(0.f, 0.f, 0.f, 0.f);

#pragma unroll 4
    for (int kc = 0; kc < 32; kc++) {
        float4 a0 = A4[(size_t)ra * 32 + kc];
        float4 a1 = A4[(size_t)rb * 32 + kc];
#pragma unroll
        for (int kk = 0; kk < 4; kk++) {
            float4 b = Bs4[(kc * 4 + kk) * 16 + tx];
            float av0 = ((const float*)&a0)[kk];
            float av1 = ((const float*)&a1)[kk];
            acc0.x = fmaf(av0, b.x, acc0.x); acc0.y = fmaf(av0, b.y, acc0.y);
            acc0.z = fmaf(av0, b.z, acc0.z); acc0.w = fmaf(av0, b.w, acc0.w);
            acc1.x = fmaf(av1, b.x, acc1.x); acc1.y = fmaf(av1, b.y, acc1.y);
            acc1.z = fmaf(av1, b.z, acc1.z); acc1.w = fmaf(av1, b.w, acc1.w);
        }
    }

    float4 bi = ((const float4*)bias)[colh * 16 + tx];
    if (r0 < n) {
        float4 o;
        o.x = acc0.x + bi.x; o.y = acc0.y + bi.y;
        o.z = acc0.z + bi.z; o.w = acc0.w + bi.w;
        ((float4*)Out)[(size_t)r0 * 32 + colh * 16 + tx] = o;
    }
    if (r0 + 1 < n) {
        float4 o;
        o.x = acc1.x + bi.x; o.y = acc1.y + bi.y;
        o.z = acc1.z + bi.z; o.w = acc1.w + bi.w;
        ((float4*)Out)[(size_t)(r0 + 1) * 32 + colh * 16 + tx] = o;
    }
}

// ---------------------------------------------------------------------------
// Kernel 2: fast-path attention. grid (NSEG, HEADS), block 1024 (32 warps).
// 4 queries per warp, PV via tiny per-warp weight staging (512B/warp).
// Segments with len > CAP are handled by seg_attn_slow.
// ---------------------------------------------------------------------------
__global__ __launch_bounds__(1024)
void seg_attn(float* __restrict__ out)
{
    extern __shared__ float sm[];
    float* Ks  = sm;                          // [CAP][33]
    float* Vs  = Ks + CAP * 33;               // [CAP][32]
    float* QsT = Vs + CAP * 32;               // [32][QST_PITCH]
    float* wb  = QsT + 32 * QST_PITCH;        // [32 warps][32][4]
    int*  rows = (int*)(wb + 32 * 32 * 4);    // [CAP]

    const int s = blockIdx.x, h = blockIdx.y;
    const int start = g_segstart[s];
    const int len = g_segstart[s + 1] - start;
    if (len == 0 || len > CAP) return;

    const int tid = threadIdx.x, lane = tid & 31, warp = tid >> 5;
    const int hoff = h * EDIM;
    const float scale = 0.17677669529663687f;   // 1/sqrt(32)

    const int nk = (len + 31) >> 5;
    const int lenp = nk * 32;

    if (tid < len) rows[tid] = g_rowlist[start + tid];
    // Stage K, V (zero-padded to lenp), Q transposed.
    for (int i = tid; i < lenp * 8; i += 1024) {
        int j = i >> 3, e4 = i & 7;
        float4 kv = make_float4(0.f, 0.f, 0.f, 0.f);
        float4 vv = kv, qv = kv;
        if (j < len) {
            int row = g_rowlist[start + j];
            const float* pk = &g_K[(size_t)row * PDIM + hoff + e4 * 4];
            const float* pv = &g_V[(size_t)row * PDIM + hoff + e4 * 4];
            const float* pq = &g_Q[(size_t)row * PDIM + hoff + e4 * 4];
            kv = *(const float4*)pk;
            vv = *(const float4*)pv;
            qv = *(const float4*)pq;
        }
        float* kd = &Ks[j * 33 + e4 * 4];
        kd[0] = kv.x; kd[1] = kv.y; kd[2] = kv.z; kd[3] = kv.w;
        *(float4*)&Vs[j * 32 + e4 * 4] = vv;
        QsT[(e4 * 4 + 0) * QST_PITCH + j] = qv.x;
        QsT[(e4 * 4 + 1) * QST_PITCH + j] = qv.y;
        QsT[(e4 * 4 + 2) * QST_PITCH + j] = qv.z;
        QsT[(e4 * 4 + 3) * QST_PITCH + j] = qv.w;
    }
    __syncthreads();

    float* wbW = wb + warp * 128;

    for (int qb = warp * 4; qb < len; qb += 128) {
        // ---- scores: lane = key within chunk, 4 queries at once ----
        float sc[4][NK_MAX];
#pragma unroll
        for (int kk = 0; kk < NK_MAX; kk++) {
            if (kk < nk) {
                int j = kk * 32 + lane;
                float a0 = 0.f, a1 = 0.f, a2 = 0.f, a3 = 0.f;
                const float* kp = &Ks[j * 33];
#pragma unroll
                for (int e = 0; e < 32; e++) {
                    float ke = kp[e];
                    float4 q4 = *(const float4*)&QsT[e * QST_PITCH + qb];
                    a0 = fmaf(ke, q4.x, a0);
                    a1 = fmaf(ke, q4.y, a1);
                    a2 = fmaf(ke, q4.z, a2);
                    a3 = fmaf(ke, q4.w, a3);
                }
                bool valid = (j < len);
                sc[0][kk] = valid ? a0 * scale : -1e30f;
                sc[1][kk] = valid ? a1 * scale : -1e30f;
                sc[2][kk] = valid ? a2 * scale : -1e30f;
                sc[3][kk] = valid ? a3 * scale : -1e30f;
            }
        }
        // ---- softmax per query ----
        float inv[4];
#pragma unroll
        for (int qi = 0; qi < 4; qi++) {
            float m = -1e30f;
#pragma unroll
            for (int kk = 0; kk < NK_MAX; kk++)
                if (kk < nk) m = fmaxf(m, sc[qi][kk]);
#pragma unroll
            for (int o = 16; o > 0; o >>= 1)
                m = fmaxf(m, __shfl_xor_sync(0xffffffffu, m, o));
            float l = 0.f;
#pragma unroll
            for (int kk = 0; kk < NK_MAX; kk++) {
                if (kk < nk) {
                    float e = __expf(sc[qi][kk] - m);
                    sc[qi][kk] = e;
                    l += e;
                }
            }
#pragma unroll
            for (int o = 16; o > 0; o >>= 1)
                l += __shfl_xor_sync(0xffffffffu, l, o);
            inv[qi] = 1.f / l;
        }
        // ---- PV in 32-key chunks through per-warp staging ----
        float a0 = 0.f, a1 = 0.f, a2 = 0.f, a3 = 0.f;
#pragma unroll
        for (int kk = 0; kk < NK_MAX; kk++) {
            if (kk < nk) {
                float4 w4;
                w4.x = sc[0][kk] * inv[0];
                w4.y = sc[1][kk] * inv[1];
                w4.z = sc[2][kk] * inv[2];
                w4.w = sc[3][kk] * inv[3];
                *(float4*)&wbW[lane * 4] = w4;
                __syncwarp();
                const float* vbase = &Vs[kk * 32 * 32 + lane];
#pragma unroll
                for (int src = 0; src < 32; src++) {
                    float v = vbase[src * 32];
                    float4 w = *(const float4*)&wbW[src * 4];
                    a0 = fmaf(w.x, v, a0); a1 = fmaf(w.y, v, a1);
                    a2 = fmaf(w.z, v, a2); a3 = fmaf(w.w, v, a3);
                }
                __syncwarp();
            }
        }

        if (qb + 0 < len) out[(size_t)rows[qb + 0] * PDIM + hoff + lane] = a0;
        if (qb + 1 < len) out[(size_t)rows[qb + 1] * PDIM + hoff + lane] = a1;
        if (qb + 2 < len) out[(size_t)rows[qb + 2] * PDIM + hoff + lane] = a2;
        if (qb + 3 < len) out[(size_t)rows[qb + 3] * PDIM + hoff + lane] = a3;
    }
}

// ---------------------------------------------------------------------------
// Kernel 3: slow-path attention for len > CAP (statistically never; early-exit).
// Separate kernel so its register usage can't hurt the fast path.
// ---------------------------------------------------------------------------
__global__ __launch_bounds__(512)
void seg_attn_slow(float* __restrict__ out)
{
    const int s = blockIdx.x, h = blockIdx.y;
    const int start = g_segstart[s];
    const int len = g_segstart[s + 1] - start;
    if (len <= CAP) return;

    __shared__ float qbuf[16][32];
    const int tid = threadIdx.x, lane = tid & 31, warp = tid >> 5;
    const int hoff = h * EDIM;
    const float scale = 0.17677669529663687f;

    for (int q = warp; q < len; q += 16) {
        const int row = g_rowlist[start + q];
        qbuf[warp][lane] = g_Q[(size_t)row * PDIM + hoff + lane];
        __syncwarp();
        float qv[32];
#pragma unroll
        for (int e = 0; e < 32; e++) qv[e] = qbuf[warp][e];

        float m = -1e30f;
        for (int j = lane; j < len; j += 32) {
            const float* kp = &g_K[(size_t)g_rowlist[start + j] * PDIM + hoff];
            float sdot = 0.f;
#pragma unroll
            for (int e = 0; e < 32; e++) sdot = fmaf(qv[e], kp[e], sdot);
            m = fmaxf(m, sdot * scale);
        }
#pragma unroll
        for (int o = 16; o > 0; o >>= 1) m = fmaxf(m, __shfl_xor_sync(0xffffffffu, m, o));

        float l = 0.f;
        float accv[32];
#pragma unroll
        for (int e = 0; e < 32; e++) accv[e] = 0.f;
        for (int j = lane; j < len; j += 32) {
            int r2 = g_rowlist[start + j];
            const float* kp = &g_K[(size_t)r2 * PDIM + hoff];
            float sdot = 0.f;
#pragma unroll
            for (int e = 0; e < 32; e++) sdot = fmaf(qv[e], kp[e], sdot);
            float w = __expf(sdot * scale - m);
            l += w;
            const float* vp = &g_V[(size_t)r2 * PDIM + hoff];
#pragma unroll
            for (int e = 0; e < 32; e++) accv[e] = fmaf(w, vp[e], accv[e]);
        }
#pragma unroll
        for (int o = 16; o > 0; o >>= 1) l += __shfl_xor_sync(0xffffffffu, l, o);
#pragma unroll
        for (int e = 0; e < 32; e++) {
            float r = accv[e];
#pragma unroll
            for (int o = 16; o > 0; o >>= 1) r += __shfl_xor_sync(0xffffffffu, r, o);
            if (lane == 0) qbuf[warp][e] = r;
        }
        __syncwarp();
        out[(size_t)row * PDIM + hoff + lane] = qbuf[warp][lane] / l;
        __syncwarp();
    }
}

// ---------------------------------------------------------------------------
extern "C" void kernel_launch(void* const* d_in, const int* in_sizes, int n_in,
                              void* d_out, int out_size)
{
    const float* inp = (const float*)d_in[0];
    const int*   pos = (const int*)d_in[1];
    const float* Wq  = (const float*)d_in[2];
    const float* bq  = (const float*)d_in[3];
    const float* Wk  = (const float*)d_in[4];
    const float* bk  = (const float*)d_in[5];
    const float* Wv  = (const float*)d_in[6];
    const float* bv  = (const float*)d_in[7];
    float* out = (float*)d_out;
    const int n = in_sizes[1];

    cudaFuncSetAttribute(qkv_build, cudaFuncAttributeMaxDynamicSharedMemorySize, QKV_SMEM_BYTES);
    cudaFuncSetAttribute(seg_attn, cudaFuncAttributeMaxDynamicSharedMemorySize, ATTN_SMEM_BYTES);

    const int row_blocks = (n + 31) / 32;
    qkv_build<<<dim3(row_blocks, 7), 256, QKV_SMEM_BYTES>>>(inp, Wq, bq, Wk, bk, Wv, bv, pos, n);
    seg_attn<<<dim3(NSEG, HEADS), 1024, ATTN_SMEM_BYTES>>>(out);
    seg_attn_slow<<<dim3(NSEG, HEADS), 512>>>(out);
}